// round 1
// baseline (speedup 1.0000x reference)
#include <cuda_runtime.h>
#include <cuda_bf16.h>
#include <cstdint>

// Problem constants (fixed shapes for NKIMoELayer_24970939859026)
#define T_TOK 4096          // B*S = 2*2048
#define HDIM  2048          // hidden
#define NEXP  16            // experts (router width)
#define TOPK  8             // top_k (reference uses experts 0..7 densely!)
#define IDIM  1408          // intermediate
#define TWOI  2816          // 2*IDIM
#define KC    (TOPK * IDIM) // 11264 — fused K dim of second GEMM

// Scratch: hid' = w[t,e] * silu(gate) * up, laid out [t, e*IDIM + i] so GEMM2
// is a single [4096,11264] x [11264,2048] GEMM (down is [E,I,H] row-major).
__device__ float g_hid[(size_t)T_TOK * KC];
__device__ float g_rw[T_TOK * TOPK];

__device__ __forceinline__ float to_tf32(float x) {
    float r;
    asm("cvt.rna.tf32.f32 %0, %1;" : "=f"(r) : "f"(x));
    return r;
}

__device__ __forceinline__ void mma_tf32(float* c, const uint32_t* a, const uint32_t* b) {
    asm volatile(
        "mma.sync.aligned.m16n8k8.row.col.f32.tf32.tf32.f32 "
        "{%0,%1,%2,%3}, {%4,%5,%6,%7}, {%8,%9}, {%0,%1,%2,%3};"
        : "+f"(c[0]), "+f"(c[1]), "+f"(c[2]), "+f"(c[3])
        : "r"(a[0]), "r"(a[1]), "r"(a[2]), "r"(a[3]), "r"(b[0]), "r"(b[1]));
}

// ---------------------------------------------------------------------------
// Router: logits = x @ router_w, softmax, top-8 values (sorted desc), norm.
// One block per token, 16 warps (one per expert logit).
// ---------------------------------------------------------------------------
__global__ __launch_bounds__(512) void router_kernel(
    const float* __restrict__ x, const float* __restrict__ rw,
    float* __restrict__ w_tail)
{
    int t = blockIdx.x;
    int wid = threadIdx.x >> 5, lane = threadIdx.x & 31;
    __shared__ float logits[NEXP];
    const float* xr = x + (size_t)t * HDIM;

    float s = 0.f;
    for (int h = lane; h < HDIM; h += 32)
        s += xr[h] * rw[h * NEXP + wid];
    #pragma unroll
    for (int o = 16; o; o >>= 1) s += __shfl_xor_sync(0xFFFFFFFFu, s, o);
    if (lane == 0) logits[wid] = s;
    __syncthreads();

    if (threadIdx.x == 0) {
        float m = logits[0];
        #pragma unroll
        for (int e = 1; e < NEXP; e++) m = fmaxf(m, logits[e]);
        float p[NEXP];
        #pragma unroll
        for (int e = 0; e < NEXP; e++) p[e] = expf(logits[e] - m);
        // top-8 values of p (selection identical to top-8 of softmax probs;
        // normalization by selected-sum cancels the softmax denominator)
        float v[TOPK]; float ssel = 0.f;
        #pragma unroll
        for (int k = 0; k < TOPK; k++) {
            int bi = 0; float bv = -1.f;
            #pragma unroll
            for (int e = 0; e < NEXP; e++)
                if (p[e] > bv) { bv = p[e]; bi = e; }
            p[bi] = -2.f; v[k] = bv; ssel += bv;
        }
        float inv = 1.f / ssel;
        #pragma unroll
        for (int k = 0; k < TOPK; k++) {
            float wv = v[k] * inv;
            g_rw[t * TOPK + k] = wv;
            if (w_tail) w_tail[t * TOPK + k] = wv;
        }
    }
}

// ---------------------------------------------------------------------------
// GEMM1: for expert e, tile of hid'[t, e*IDIM + i]:
//   gate = X @ GU_e[:, i], up = X @ GU_e[:, IDIM+i]
//   hid' = w[t,e] * silu(gate) * up
// BM=128, BN=64 (per half, gate+up both computed), BK=32, 256 thr (8 warps 4x2)
// ---------------------------------------------------------------------------
#define G1_BM 128
#define G1_BN 64
#define G1_BK 32

__global__ __launch_bounds__(256) void gemm1_kernel(
    const float* __restrict__ X,   // [4096, 2048]
    const float* __restrict__ GU)  // [16, 2048, 2816]
{
    const int m0 = blockIdx.x * G1_BM;
    const int n0 = blockIdx.y * G1_BN;
    const int e  = blockIdx.z;
    const float* gu = GU + (size_t)e * HDIM * TWOI;

    __shared__ float sA[G1_BM][G1_BK + 4];   // [m][k]
    __shared__ float sG[G1_BK][G1_BN + 4];   // [k][n]
    __shared__ float sU[G1_BK][G1_BN + 4];

    const int tid = threadIdx.x;
    const int wid = tid >> 5, lane = tid & 31;
    const int wm = wid & 3, wn = wid >> 2;       // 4 x 2 warps
    const int g = lane >> 2, tg = lane & 3;

    float accG[2][4][4] = {};
    float accU[2][4][4] = {};

    for (int kk = 0; kk < HDIM; kk += G1_BK) {
        // A tile: 128x32 = 1024 float4, 4 per thread
        #pragma unroll
        for (int i = 0; i < 4; i++) {
            int idx = tid + i * 256;
            int m = idx >> 3, k4 = idx & 7;
            float4 v = *(const float4*)(X + (size_t)(m0 + m) * HDIM + kk + k4 * 4);
            sA[m][k4*4+0] = to_tf32(v.x); sA[m][k4*4+1] = to_tf32(v.y);
            sA[m][k4*4+2] = to_tf32(v.z); sA[m][k4*4+3] = to_tf32(v.w);
        }
        // gate / up tiles: each 32(k) x 64(n) = 512 float4, 2 per thread
        #pragma unroll
        for (int i = 0; i < 2; i++) {
            int idx = tid + i * 256;
            int k = idx >> 4, n4 = idx & 15;
            const float* src = gu + (size_t)(kk + k) * TWOI + n0 + n4 * 4;
            float4 vg = *(const float4*)(src);
            float4 vu = *(const float4*)(src + IDIM);
            float4 cg = make_float4(to_tf32(vg.x), to_tf32(vg.y), to_tf32(vg.z), to_tf32(vg.w));
            float4 cu = make_float4(to_tf32(vu.x), to_tf32(vu.y), to_tf32(vu.z), to_tf32(vu.w));
            *(float4*)&sG[k][n4*4] = cg;
            *(float4*)&sU[k][n4*4] = cu;
        }
        __syncthreads();

        #pragma unroll
        for (int ks = 0; ks < G1_BK / 8; ks++) {
            int k0 = ks * 8;
            uint32_t afr[2][4];
            #pragma unroll
            for (int mi = 0; mi < 2; mi++) {
                int row = wm * 32 + mi * 16;
                afr[mi][0] = __float_as_uint(sA[row + g    ][k0 + tg]);
                afr[mi][1] = __float_as_uint(sA[row + g + 8][k0 + tg]);
                afr[mi][2] = __float_as_uint(sA[row + g    ][k0 + tg + 4]);
                afr[mi][3] = __float_as_uint(sA[row + g + 8][k0 + tg + 4]);
            }
            #pragma unroll
            for (int ni = 0; ni < 4; ni++) {
                int col = wn * 32 + ni * 8 + g;
                uint32_t bg[2], bu[2];
                bg[0] = __float_as_uint(sG[k0 + tg    ][col]);
                bg[1] = __float_as_uint(sG[k0 + tg + 4][col]);
                bu[0] = __float_as_uint(sU[k0 + tg    ][col]);
                bu[1] = __float_as_uint(sU[k0 + tg + 4][col]);
                #pragma unroll
                for (int mi = 0; mi < 2; mi++) {
                    mma_tf32(accG[mi][ni], afr[mi], bg);
                    mma_tf32(accU[mi][ni], afr[mi], bu);
                }
            }
        }
        __syncthreads();
    }

    // Epilogue: hid' = w * silu(gate) * up
    #pragma unroll
    for (int mi = 0; mi < 2; mi++) {
        #pragma unroll
        for (int r2 = 0; r2 < 2; r2++) {
            int t = m0 + wm * 32 + mi * 16 + g + r2 * 8;
            float w = g_rw[t * TOPK + e];
            size_t rowoff = (size_t)t * KC + (size_t)e * IDIM + n0;
            #pragma unroll
            for (int ni = 0; ni < 4; ni++) {
                int col = wn * 32 + ni * 8 + tg * 2;
                #pragma unroll
                for (int cj = 0; cj < 2; cj++) {
                    float gv = accG[mi][ni][r2 * 2 + cj];
                    float uv = accU[mi][ni][r2 * 2 + cj];
                    float sil = gv / (1.f + expf(-gv));
                    g_hid[rowoff + col + cj] = sil * uv * w;
                }
            }
        }
    }
}

// ---------------------------------------------------------------------------
// GEMM2: out[4096,2048] = hid'[4096,11264] @ down_flat[11264,2048]
// BM=128, BN=128, BK=32, 256 thr (8 warps 4x2), warp tile 32x64
// ---------------------------------------------------------------------------
__global__ __launch_bounds__(256) void gemm2_kernel(
    const float* __restrict__ DW,  // [11264, 2048]  (down [8,1408,2048] flat)
    float* __restrict__ OUT)       // [4096, 2048]
{
    const int m0 = blockIdx.x * 128;
    const int n0 = blockIdx.y * 128;

    __shared__ float sA[128][36];       // [m][k]
    __shared__ float sB[32][132];       // [k][n]

    const int tid = threadIdx.x;
    const int wid = tid >> 5, lane = tid & 31;
    const int wm = wid & 3, wn = wid >> 2;
    const int g = lane >> 2, tg = lane & 3;

    float acc[2][8][4] = {};

    for (int kk = 0; kk < KC; kk += 32) {
        #pragma unroll
        for (int i = 0; i < 4; i++) {
            int idx = tid + i * 256;
            int m = idx >> 3, k4 = idx & 7;
            float4 v = *(const float4*)(g_hid + (size_t)(m0 + m) * KC + kk + k4 * 4);
            sA[m][k4*4+0] = to_tf32(v.x); sA[m][k4*4+1] = to_tf32(v.y);
            sA[m][k4*4+2] = to_tf32(v.z); sA[m][k4*4+3] = to_tf32(v.w);
        }
        #pragma unroll
        for (int i = 0; i < 4; i++) {
            int idx = tid + i * 256;
            int k = idx >> 5, n4 = idx & 31;
            float4 v = *(const float4*)(DW + (size_t)(kk + k) * HDIM + n0 + n4 * 4);
            float4 c = make_float4(to_tf32(v.x), to_tf32(v.y), to_tf32(v.z), to_tf32(v.w));
            *(float4*)&sB[k][n4*4] = c;
        }
        __syncthreads();

        #pragma unroll
        for (int ks = 0; ks < 4; ks++) {
            int k0 = ks * 8;
            uint32_t afr[2][4];
            #pragma unroll
            for (int mi = 0; mi < 2; mi++) {
                int row = wm * 32 + mi * 16;
                afr[mi][0] = __float_as_uint(sA[row + g    ][k0 + tg]);
                afr[mi][1] = __float_as_uint(sA[row + g + 8][k0 + tg]);
                afr[mi][2] = __float_as_uint(sA[row + g    ][k0 + tg + 4]);
                afr[mi][3] = __float_as_uint(sA[row + g + 8][k0 + tg + 4]);
            }
            #pragma unroll
            for (int ni = 0; ni < 8; ni++) {
                int col = wn * 64 + ni * 8 + g;
                uint32_t b[2];
                b[0] = __float_as_uint(sB[k0 + tg    ][col]);
                b[1] = __float_as_uint(sB[k0 + tg + 4][col]);
                #pragma unroll
                for (int mi = 0; mi < 2; mi++)
                    mma_tf32(acc[mi][ni], afr[mi], b);
            }
        }
        __syncthreads();
    }

    // Epilogue: plain fp32 store
    #pragma unroll
    for (int mi = 0; mi < 2; mi++) {
        #pragma unroll
        for (int r2 = 0; r2 < 2; r2++) {
            int t = m0 + wm * 32 + mi * 16 + g + r2 * 8;
            #pragma unroll
            for (int ni = 0; ni < 8; ni++) {
                int col = n0 + wn * 64 + ni * 8 + tg * 2;
                float2 v;
                v.x = acc[mi][ni][r2 * 2 + 0];
                v.y = acc[mi][ni][r2 * 2 + 1];
                *(float2*)(OUT + (size_t)t * HDIM + col) = v;
            }
        }
    }
}

// ---------------------------------------------------------------------------
extern "C" void kernel_launch(void* const* d_in, const int* in_sizes, int n_in,
                              void* d_out, int out_size) {
    const float* x  = (const float*)d_in[0];   // hidden_states [2,2048,2048]
    const float* rw = (const float*)d_in[1];   // router_w [2048,16]
    const float* gu = (const float*)d_in[2];   // gate_up [16,2048,2816]
    const float* dw = (const float*)d_in[3];   // down [16,1408,2048]
    float* out = (float*)d_out;

    // Reference returns (out, routing_weights); if the output buffer has room
    // for both, write routing weights to the tail.
    const long long OUT_ELEMS = (long long)T_TOK * HDIM;   // 8388608
    float* tail = nullptr;
    if ((long long)out_size >= OUT_ELEMS + (long long)T_TOK * TOPK)
        tail = out + OUT_ELEMS;

    router_kernel<<<T_TOK, 512>>>(x, rw, tail);

    dim3 grid1(T_TOK / G1_BM, IDIM / G1_BN, TOPK);   // (32, 22, 8), m fastest
    gemm1_kernel<<<grid1, 256>>>(x, gu);

    dim3 grid2(T_TOK / 128, HDIM / 128);             // (32, 16), m fastest
    gemm2_kernel<<<grid2, 256>>>(dw, out);
}

// round 2
// speedup vs baseline: 1.3036x; 1.3036x over previous
#include <cuda_runtime.h>
#include <cuda_bf16.h>
#include <cstdint>

// Problem constants (fixed shapes for NKIMoELayer_24970939859026)
#define T_TOK 4096          // B*S
#define HDIM  2048
#define NEXP  16
#define TOPK  8             // reference uses experts 0..7 densely
#define IDIM  1408
#define TWOI  2816
#define KC    (TOPK * IDIM) // 11264

// Scratch (__device__ globals: allocation-free rule)
__device__ float g_hid[(size_t)T_TOK * KC];                 // tf32-rounded hid'
__device__ float g_rw [T_TOK * TOPK];
__device__ float g_xt [(size_t)T_TOK * HDIM];               // tf32(X)
__device__ float g_gut[(size_t)TOPK * HDIM * TWOI];         // tf32(gate_up[0:8])
__device__ float g_dwt[(size_t)KC * HDIM];                  // tf32(down[0:8] flat)

__device__ __forceinline__ float to_tf32(float x) {
    float r;
    asm("cvt.rna.tf32.f32 %0, %1;" : "=f"(r) : "f"(x));
    return r;
}

__device__ __forceinline__ void mma_tf32(float* c, const uint32_t* a, const uint32_t* b) {
    asm volatile(
        "mma.sync.aligned.m16n8k8.row.col.f32.tf32.tf32.f32 "
        "{%0,%1,%2,%3}, {%4,%5,%6,%7}, {%8,%9}, {%0,%1,%2,%3};"
        : "+f"(c[0]), "+f"(c[1]), "+f"(c[2]), "+f"(c[3])
        : "r"(a[0]), "r"(a[1]), "r"(a[2]), "r"(a[3]), "r"(b[0]), "r"(b[1]));
}

__device__ __forceinline__ void cp_async16(void* smem, const void* gmem) {
    uint32_t s = (uint32_t)__cvta_generic_to_shared(smem);
    asm volatile("cp.async.cg.shared.global [%0], [%1], 16;" :: "r"(s), "l"(gmem));
}
__device__ __forceinline__ void cp_commit() { asm volatile("cp.async.commit_group;"); }
template<int N> __device__ __forceinline__ void cp_wait() {
    asm volatile("cp.async.wait_group %0;" :: "n"(N));
}

// ---------------------------------------------------------------------------
// Pre-convert fp32 -> tf32-rounded fp32 (enables cvt-free cp.async GEMMs)
// ---------------------------------------------------------------------------
__global__ __launch_bounds__(256) void cvt_x_kernel(const float* __restrict__ src) {
    const long long n4 = (long long)T_TOK * HDIM / 4;
    long long i = (long long)blockIdx.x * blockDim.x + threadIdx.x;
    long long st = (long long)gridDim.x * blockDim.x;
    for (; i < n4; i += st) {
        float4 v = ((const float4*)src)[i];
        ((float4*)g_xt)[i] = make_float4(to_tf32(v.x), to_tf32(v.y), to_tf32(v.z), to_tf32(v.w));
    }
}
__global__ __launch_bounds__(256) void cvt_gu_kernel(const float* __restrict__ src) {
    const long long n4 = (long long)TOPK * HDIM * TWOI / 4;
    long long i = (long long)blockIdx.x * blockDim.x + threadIdx.x;
    long long st = (long long)gridDim.x * blockDim.x;
    for (; i < n4; i += st) {
        float4 v = ((const float4*)src)[i];
        ((float4*)g_gut)[i] = make_float4(to_tf32(v.x), to_tf32(v.y), to_tf32(v.z), to_tf32(v.w));
    }
}
__global__ __launch_bounds__(256) void cvt_dw_kernel(const float* __restrict__ src) {
    const long long n4 = (long long)KC * HDIM / 4;
    long long i = (long long)blockIdx.x * blockDim.x + threadIdx.x;
    long long st = (long long)gridDim.x * blockDim.x;
    for (; i < n4; i += st) {
        float4 v = ((const float4*)src)[i];
        ((float4*)g_dwt)[i] = make_float4(to_tf32(v.x), to_tf32(v.y), to_tf32(v.z), to_tf32(v.w));
    }
}

// ---------------------------------------------------------------------------
// Router: one warp per token; rw rows (64B) coalesce across lanes.
// ---------------------------------------------------------------------------
__global__ __launch_bounds__(256) void router_kernel(
    const float* __restrict__ x, const float* __restrict__ rw,
    float* __restrict__ w_tail)
{
    int t = (blockIdx.x * blockDim.x + threadIdx.x) >> 5;
    int lane = threadIdx.x & 31;
    if (t >= T_TOK) return;
    const float* xr = x + (size_t)t * HDIM;

    float acc[NEXP] = {};
    for (int h = lane; h < HDIM; h += 32) {
        float xv = xr[h];
        const float4* r4 = (const float4*)(rw + (size_t)h * NEXP);
        float4 a = r4[0], b = r4[1], c = r4[2], d = r4[3];
        acc[0]  += xv * a.x; acc[1]  += xv * a.y; acc[2]  += xv * a.z; acc[3]  += xv * a.w;
        acc[4]  += xv * b.x; acc[5]  += xv * b.y; acc[6]  += xv * b.z; acc[7]  += xv * b.w;
        acc[8]  += xv * c.x; acc[9]  += xv * c.y; acc[10] += xv * c.z; acc[11] += xv * c.w;
        acc[12] += xv * d.x; acc[13] += xv * d.y; acc[14] += xv * d.z; acc[15] += xv * d.w;
    }
    #pragma unroll
    for (int e = 0; e < NEXP; e++) {
        #pragma unroll
        for (int o = 16; o; o >>= 1) acc[e] += __shfl_xor_sync(0xFFFFFFFFu, acc[e], o);
    }
    if (lane == 0) {
        float m = acc[0];
        #pragma unroll
        for (int e = 1; e < NEXP; e++) m = fmaxf(m, acc[e]);
        float p[NEXP];
        #pragma unroll
        for (int e = 0; e < NEXP; e++) p[e] = expf(acc[e] - m);
        float v[TOPK]; float ssel = 0.f;
        #pragma unroll
        for (int k = 0; k < TOPK; k++) {
            int bi = 0; float bv = -1.f;
            #pragma unroll
            for (int e = 0; e < NEXP; e++)
                if (p[e] > bv) { bv = p[e]; bi = e; }
            p[bi] = -2.f; v[k] = bv; ssel += bv;
        }
        float inv = 1.f / ssel;
        #pragma unroll
        for (int k = 0; k < TOPK; k++) {
            float wv = v[k] * inv;
            g_rw[t * TOPK + k] = wv;
            if (w_tail) w_tail[t * TOPK + k] = wv;
        }
    }
}

// ---------------------------------------------------------------------------
// GEMM1: hid'[t, e*IDIM+n] = w[t,e] * silu(X@GUe[:,n]) * (X@GUe[:,IDIM+n])
// BM=128, BN=64 (gate+up), BK=32, 3-stage cp.async, 256 thr (8 warps 4x2)
// ---------------------------------------------------------------------------
#define NSTAGE 3
#define G1_AS  (128 * 36)
#define G1_GS  (32 * 72)
#define G1_STAGE (G1_AS + 2 * G1_GS)
#define G1_SMEM (NSTAGE * G1_STAGE * 4)

__global__ __launch_bounds__(256) void gemm1_kernel()
{
    extern __shared__ float sm[];
    const int m0 = blockIdx.x * 128;
    const int n0 = blockIdx.y * 64;
    const int e  = blockIdx.z;
    const float* gu = g_gut + (size_t)e * HDIM * TWOI;

    const int tid = threadIdx.x;
    const int wid = tid >> 5, lane = tid & 31;
    const int wm = wid & 3, wn = wid >> 2;
    const int g = lane >> 2, tg = lane & 3;

    float accG[2][4][4] = {};
    float accU[2][4][4] = {};

    const int KITER = HDIM / 32;   // 64

    // ---- prologue: fill NSTAGE-1 stages ----
    #pragma unroll
    for (int s = 0; s < NSTAGE - 1; s++) {
        float* A = sm + s * G1_STAGE;
        float* G = A + G1_AS;
        float* U = G + G1_GS;
        int kk = s * 32;
        #pragma unroll
        for (int i = 0; i < 4; i++) {
            int idx = tid + i * 256;
            int m = idx >> 3, k4 = idx & 7;
            cp_async16(A + m * 36 + k4 * 4, g_xt + (size_t)(m0 + m) * HDIM + kk + k4 * 4);
        }
        #pragma unroll
        for (int i = 0; i < 2; i++) {
            int idx = tid + i * 256;
            int k = idx >> 4, n4 = idx & 15;
            const float* src = gu + (size_t)(kk + k) * TWOI + n0 + n4 * 4;
            cp_async16(G + k * 72 + n4 * 4, src);
            cp_async16(U + k * 72 + n4 * 4, src + IDIM);
        }
        cp_commit();
    }

    for (int it = 0; it < KITER; it++) {
        cp_wait<NSTAGE - 2>();
        __syncthreads();

        int nxt = it + NSTAGE - 1;
        if (nxt < KITER) {
            int s = nxt % NSTAGE;
            float* A = sm + s * G1_STAGE;
            float* G = A + G1_AS;
            float* U = G + G1_GS;
            int kk = nxt * 32;
            #pragma unroll
            for (int i = 0; i < 4; i++) {
                int idx = tid + i * 256;
                int m = idx >> 3, k4 = idx & 7;
                cp_async16(A + m * 36 + k4 * 4, g_xt + (size_t)(m0 + m) * HDIM + kk + k4 * 4);
            }
            #pragma unroll
            for (int i = 0; i < 2; i++) {
                int idx = tid + i * 256;
                int k = idx >> 4, n4 = idx & 15;
                const float* src = gu + (size_t)(kk + k) * TWOI + n0 + n4 * 4;
                cp_async16(G + k * 72 + n4 * 4, src);
                cp_async16(U + k * 72 + n4 * 4, src + IDIM);
            }
        }
        cp_commit();

        const float* A = sm + (it % NSTAGE) * G1_STAGE;
        const float* G = A + G1_AS;
        const float* U = G + G1_GS;

        #pragma unroll
        for (int ks = 0; ks < 4; ks++) {
            int k0 = ks * 8;
            uint32_t afr[2][4];
            #pragma unroll
            for (int mi = 0; mi < 2; mi++) {
                int row = wm * 32 + mi * 16;
                afr[mi][0] = __float_as_uint(A[(row + g    ) * 36 + k0 + tg    ]);
                afr[mi][1] = __float_as_uint(A[(row + g + 8) * 36 + k0 + tg    ]);
                afr[mi][2] = __float_as_uint(A[(row + g    ) * 36 + k0 + tg + 4]);
                afr[mi][3] = __float_as_uint(A[(row + g + 8) * 36 + k0 + tg + 4]);
            }
            #pragma unroll
            for (int ni = 0; ni < 4; ni++) {
                int col = wn * 32 + ni * 8 + g;
                uint32_t bg[2], bu[2];
                bg[0] = __float_as_uint(G[(k0 + tg    ) * 72 + col]);
                bg[1] = __float_as_uint(G[(k0 + tg + 4) * 72 + col]);
                bu[0] = __float_as_uint(U[(k0 + tg    ) * 72 + col]);
                bu[1] = __float_as_uint(U[(k0 + tg + 4) * 72 + col]);
                #pragma unroll
                for (int mi = 0; mi < 2; mi++) {
                    mma_tf32(accG[mi][ni], afr[mi], bg);
                    mma_tf32(accU[mi][ni], afr[mi], bu);
                }
            }
        }
    }

    // Epilogue: hid' = w * silu(gate) * up, stored tf32-rounded
    #pragma unroll
    for (int mi = 0; mi < 2; mi++) {
        #pragma unroll
        for (int r2 = 0; r2 < 2; r2++) {
            int t = m0 + wm * 32 + mi * 16 + g + r2 * 8;
            float w = g_rw[t * TOPK + e];
            size_t rowoff = (size_t)t * KC + (size_t)e * IDIM + n0;
            #pragma unroll
            for (int ni = 0; ni < 4; ni++) {
                int col = wn * 32 + ni * 8 + tg * 2;
                #pragma unroll
                for (int cj = 0; cj < 2; cj++) {
                    float gv = accG[mi][ni][r2 * 2 + cj];
                    float uv = accU[mi][ni][r2 * 2 + cj];
                    float sil = gv / (1.f + expf(-gv));
                    g_hid[rowoff + col + cj] = to_tf32(sil * uv * w);
                }
            }
        }
    }
}

// ---------------------------------------------------------------------------
// GEMM2: out[4096,2048] = g_hid[4096,11264] @ g_dwt[11264,2048]
// BM=128, BN=128, BK=32, 3-stage cp.async, 256 thr, warp 32x64
// ---------------------------------------------------------------------------
#define G2_AS (128 * 36)
#define G2_BS (32 * 136)
#define G2_STAGE (G2_AS + G2_BS)
#define G2_SMEM (NSTAGE * G2_STAGE * 4)

__global__ __launch_bounds__(256) void gemm2_kernel(float* __restrict__ OUT)
{
    extern __shared__ float sm[];
    const int m0 = blockIdx.x * 128;
    const int n0 = blockIdx.y * 128;

    const int tid = threadIdx.x;
    const int wid = tid >> 5, lane = tid & 31;
    const int wm = wid & 3, wn = wid >> 2;
    const int g = lane >> 2, tg = lane & 3;

    float acc[2][8][4] = {};

    const int KITER = KC / 32;   // 352

    #pragma unroll
    for (int s = 0; s < NSTAGE - 1; s++) {
        float* A = sm + s * G2_STAGE;
        float* B = A + G2_AS;
        int kk = s * 32;
        #pragma unroll
        for (int i = 0; i < 4; i++) {
            int idx = tid + i * 256;
            int m = idx >> 3, k4 = idx & 7;
            cp_async16(A + m * 36 + k4 * 4, g_hid + (size_t)(m0 + m) * KC + kk + k4 * 4);
        }
        #pragma unroll
        for (int i = 0; i < 4; i++) {
            int idx = tid + i * 256;
            int k = idx >> 5, n4 = idx & 31;
            cp_async16(B + k * 136 + n4 * 4, g_dwt + (size_t)(kk + k) * HDIM + n0 + n4 * 4);
        }
        cp_commit();
    }

    for (int it = 0; it < KITER; it++) {
        cp_wait<NSTAGE - 2>();
        __syncthreads();

        int nxt = it + NSTAGE - 1;
        if (nxt < KITER) {
            int s = nxt % NSTAGE;
            float* A = sm + s * G2_STAGE;
            float* B = A + G2_AS;
            int kk = nxt * 32;
            #pragma unroll
            for (int i = 0; i < 4; i++) {
                int idx = tid + i * 256;
                int m = idx >> 3, k4 = idx & 7;
                cp_async16(A + m * 36 + k4 * 4, g_hid + (size_t)(m0 + m) * KC + kk + k4 * 4);
            }
            #pragma unroll
            for (int i = 0; i < 4; i++) {
                int idx = tid + i * 256;
                int k = idx >> 5, n4 = idx & 31;
                cp_async16(B + k * 136 + n4 * 4, g_dwt + (size_t)(kk + k) * HDIM + n0 + n4 * 4);
            }
        }
        cp_commit();

        const float* A = sm + (it % NSTAGE) * G2_STAGE;
        const float* B = A + G2_AS;

        #pragma unroll
        for (int ks = 0; ks < 4; ks++) {
            int k0 = ks * 8;
            uint32_t afr[2][4];
            #pragma unroll
            for (int mi = 0; mi < 2; mi++) {
                int row = wm * 32 + mi * 16;
                afr[mi][0] = __float_as_uint(A[(row + g    ) * 36 + k0 + tg    ]);
                afr[mi][1] = __float_as_uint(A[(row + g + 8) * 36 + k0 + tg    ]);
                afr[mi][2] = __float_as_uint(A[(row + g    ) * 36 + k0 + tg + 4]);
                afr[mi][3] = __float_as_uint(A[(row + g + 8) * 36 + k0 + tg + 4]);
            }
            #pragma unroll
            for (int ni = 0; ni < 8; ni++) {
                int col = wn * 64 + ni * 8 + g;
                uint32_t b[2];
                b[0] = __float_as_uint(B[(k0 + tg    ) * 136 + col]);
                b[1] = __float_as_uint(B[(k0 + tg + 4) * 136 + col]);
                #pragma unroll
                for (int mi = 0; mi < 2; mi++)
                    mma_tf32(acc[mi][ni], afr[mi], b);
            }
        }
    }

    #pragma unroll
    for (int mi = 0; mi < 2; mi++) {
        #pragma unroll
        for (int r2 = 0; r2 < 2; r2++) {
            int t = m0 + wm * 32 + mi * 16 + g + r2 * 8;
            #pragma unroll
            for (int ni = 0; ni < 8; ni++) {
                int col = n0 + wn * 64 + ni * 8 + tg * 2;
                float2 v;
                v.x = acc[mi][ni][r2 * 2 + 0];
                v.y = acc[mi][ni][r2 * 2 + 1];
                *(float2*)(OUT + (size_t)t * HDIM + col) = v;
            }
        }
    }
}

// ---------------------------------------------------------------------------
extern "C" void kernel_launch(void* const* d_in, const int* in_sizes, int n_in,
                              void* d_out, int out_size) {
    const float* x  = (const float*)d_in[0];
    const float* rw = (const float*)d_in[1];
    const float* gu = (const float*)d_in[2];
    const float* dw = (const float*)d_in[3];
    float* out = (float*)d_out;

    const long long OUT_ELEMS = (long long)T_TOK * HDIM;
    float* tail = nullptr;
    if ((long long)out_size >= OUT_ELEMS + (long long)T_TOK * TOPK)
        tail = out + OUT_ELEMS;

    static bool attr_done = false;
    if (!attr_done) {
        cudaFuncSetAttribute(gemm1_kernel, cudaFuncAttributeMaxDynamicSharedMemorySize, G1_SMEM);
        cudaFuncSetAttribute(gemm2_kernel, cudaFuncAttributeMaxDynamicSharedMemorySize, G2_SMEM);
        attr_done = true;
    }

    cvt_x_kernel <<<2048, 256>>>(x);
    cvt_gu_kernel<<<8192, 256>>>(gu);
    cvt_dw_kernel<<<8192, 256>>>(dw);
    router_kernel<<<T_TOK / 8, 256>>>(x, rw, tail);

    dim3 grid1(T_TOK / 128, IDIM / 64, TOPK);   // (32, 22, 8)
    gemm1_kernel<<<grid1, 256, G1_SMEM>>>();

    dim3 grid2(T_TOK / 128, HDIM / 128);        // (32, 16)
    gemm2_kernel<<<grid2, 256, G2_SMEM>>>(out);
}

// round 5
// speedup vs baseline: 2.3320x; 1.7889x over previous
#include <cuda_runtime.h>
#include <cuda_fp16.h>
#include <cstdint>

// Fixed shapes for NKIMoELayer_24970939859026
#define T_TOK 4096
#define HDIM  2048
#define NEXP  16
#define TOPK  8             // reference uses experts 0..7 densely
#define IDIM  1408
#define TWOI  2816
#define KC    (TOPK * IDIM) // 11264

// Scratch (__device__ globals: allocation-free rule)
__device__ __half g_hid[(size_t)T_TOK * KC];          // hid' fp16       [t][e*IDIM+i]
__device__ float  g_rw [T_TOK * TOPK];
__device__ __half g_xh [(size_t)T_TOK * HDIM];        // fp16(X)         [t][h]
__device__ __half g_guh[(size_t)TOPK * TWOI * HDIM];  // fp16(gate_up^T) [e][feat][h]
__device__ __half g_dwh[(size_t)HDIM * KC];           // fp16(down^T)    [n][k]

__device__ __forceinline__ void mma_f16(float* c, const uint32_t* a, const uint32_t* b) {
    asm volatile(
        "mma.sync.aligned.m16n8k16.row.col.f32.f16.f16.f32 "
        "{%0,%1,%2,%3}, {%4,%5,%6,%7}, {%8,%9}, {%0,%1,%2,%3};"
        : "+f"(c[0]), "+f"(c[1]), "+f"(c[2]), "+f"(c[3])
        : "r"(a[0]), "r"(a[1]), "r"(a[2]), "r"(a[3]), "r"(b[0]), "r"(b[1]));
}

__device__ __forceinline__ void cp_async16(void* smem, const void* gmem) {
    uint32_t s = (uint32_t)__cvta_generic_to_shared(smem);
    asm volatile("cp.async.cg.shared.global [%0], [%1], 16;" :: "r"(s), "l"(gmem));
}
__device__ __forceinline__ void cp_commit() { asm volatile("cp.async.commit_group;"); }
template<int N> __device__ __forceinline__ void cp_wait() {
    asm volatile("cp.async.wait_group %0;" :: "n"(N));
}

// XOR-swizzled tile: row stride 64B (32 halves), 4 chunks of 16B per row.
// Stored chunk position = c ^ ((row>>1)&3).
__device__ __forceinline__ uint32_t sw_store(int row, int c) {
    return (uint32_t)(row * 64 + ((c ^ ((row >> 1) & 3)) << 4));
}
// 32-bit load of halves [k, k+1] of logical row `row`.
__device__ __forceinline__ uint32_t ld32_sw(const char* tile, int row, int k) {
    uint32_t chunkpos = (uint32_t)(((k >> 3) ^ ((row >> 1) & 3)) << 4);
    uint32_t off = (uint32_t)(row * 64) + chunkpos + (uint32_t)((k * 2) & 15);
    return *(const uint32_t*)(tile + off);
}

// ---------------------------------------------------------------------------
// Pre-pass: fp32 -> fp16 convert / transpose
// ---------------------------------------------------------------------------
__global__ __launch_bounds__(256) void cvt_x_kernel(const float* __restrict__ src) {
    const long long n4 = (long long)T_TOK * HDIM / 4;
    long long i = (long long)blockIdx.x * blockDim.x + threadIdx.x;
    long long st = (long long)gridDim.x * blockDim.x;
    for (; i < n4; i += st) {
        float4 v = ((const float4*)src)[i];
        ((__half2*)g_xh)[i * 2 + 0] = __floats2half2_rn(v.x, v.y);
        ((__half2*)g_xh)[i * 2 + 1] = __floats2half2_rn(v.z, v.w);
    }
}
// gate_up[e][h][n] -> g_guh[e][n][h]
__global__ __launch_bounds__(256) void tpose_gu_kernel(const float* __restrict__ src) {
    __shared__ float tile[32][33];
    int e = blockIdx.z, n0 = blockIdx.x * 32, h0 = blockIdx.y * 32;
    int tx = threadIdx.x, ty = threadIdx.y;
    #pragma unroll
    for (int r = ty; r < 32; r += 8)
        tile[r][tx] = src[((size_t)e * HDIM + h0 + r) * TWOI + n0 + tx];
    __syncthreads();
    #pragma unroll
    for (int r = ty; r < 32; r += 8)
        g_guh[((size_t)e * TWOI + n0 + r) * HDIM + h0 + tx] = __float2half_rn(tile[tx][r]);
}
// down[e][i][h] -> g_dwh[h][e*IDIM+i]
__global__ __launch_bounds__(256) void tpose_dw_kernel(const float* __restrict__ src) {
    __shared__ float tile[32][33];
    int e = blockIdx.z, i0 = blockIdx.x * 32, h0 = blockIdx.y * 32;
    int tx = threadIdx.x, ty = threadIdx.y;
    #pragma unroll
    for (int r = ty; r < 32; r += 8)
        tile[r][tx] = src[((size_t)e * IDIM + i0 + r) * HDIM + h0 + tx];
    __syncthreads();
    #pragma unroll
    for (int r = ty; r < 32; r += 8)
        g_dwh[(size_t)(h0 + r) * KC + (size_t)e * IDIM + i0 + tx] = __float2half_rn(tile[tx][r]);
}

// ---------------------------------------------------------------------------
// Router: one warp per token
// ---------------------------------------------------------------------------
__global__ __launch_bounds__(256) void router_kernel(
    const float* __restrict__ x, const float* __restrict__ rw, float* __restrict__ w_tail)
{
    int t = (blockIdx.x * blockDim.x + threadIdx.x) >> 5;
    int lane = threadIdx.x & 31;
    if (t >= T_TOK) return;
    const float* xr = x + (size_t)t * HDIM;
    float acc[NEXP] = {};
    for (int h = lane; h < HDIM; h += 32) {
        float xv = xr[h];
        const float4* r4 = (const float4*)(rw + (size_t)h * NEXP);
        float4 a = r4[0], b = r4[1], c = r4[2], d = r4[3];
        acc[0]+=xv*a.x; acc[1]+=xv*a.y; acc[2]+=xv*a.z; acc[3]+=xv*a.w;
        acc[4]+=xv*b.x; acc[5]+=xv*b.y; acc[6]+=xv*b.z; acc[7]+=xv*b.w;
        acc[8]+=xv*c.x; acc[9]+=xv*c.y; acc[10]+=xv*c.z; acc[11]+=xv*c.w;
        acc[12]+=xv*d.x; acc[13]+=xv*d.y; acc[14]+=xv*d.z; acc[15]+=xv*d.w;
    }
    #pragma unroll
    for (int e = 0; e < NEXP; e++) {
        #pragma unroll
        for (int o = 16; o; o >>= 1) acc[e] += __shfl_xor_sync(0xFFFFFFFFu, acc[e], o);
    }
    if (lane == 0) {
        float m = acc[0];
        #pragma unroll
        for (int e = 1; e < NEXP; e++) m = fmaxf(m, acc[e]);
        float p[NEXP];
        #pragma unroll
        for (int e = 0; e < NEXP; e++) p[e] = expf(acc[e] - m);
        float v[TOPK]; float ssel = 0.f;
        #pragma unroll
        for (int k = 0; k < TOPK; k++) {
            int bi = 0; float bv = -1.f;
            #pragma unroll
            for (int e = 0; e < NEXP; e++) if (p[e] > bv) { bv = p[e]; bi = e; }
            p[bi] = -2.f; v[k] = bv; ssel += bv;
        }
        float inv = 1.f / ssel;
        #pragma unroll
        for (int k = 0; k < TOPK; k++) {
            float wv = v[k] * inv;
            g_rw[t * TOPK + k] = wv;
            if (w_tail) w_tail[t * TOPK + k] = wv;
        }
    }
}

#define NSTAGE 3
#define STAGE_B 16384   // A tile 8 KB (128 rows x 64B) + B region 8 KB

// ---------------------------------------------------------------------------
// GEMM1: hid'[t, e*IDIM+n] = w[t,e] * silu(X@GUe[:,n]) * (X@GUe[:,IDIM+n])
// BM=128, BN=64(gate)+64(up), BK=32 halves. 8 warps (4x2), warp 32x32(+32x32).
// ---------------------------------------------------------------------------
__global__ __launch_bounds__(256) void gemm1_kernel()
{
    __shared__ __align__(128) char smem[NSTAGE * STAGE_B];
    const int m0 = blockIdx.x * 128;
    const int n0 = blockIdx.y * 64;
    const int e  = blockIdx.z;
    const __half* Bbase = g_guh + (size_t)e * TWOI * HDIM;

    const int tid = threadIdx.x;
    const int wid = tid >> 5, lane = tid & 31;
    const int wm = wid & 3, wn = wid >> 2;
    const int g = lane >> 2, tg = lane & 3;

    float accG[2][4][4] = {};
    float accU[2][4][4] = {};
    const int KITER = HDIM / 32;   // 64

    auto load_stage = [&](int s, int kk) {
        char* st = smem + s * STAGE_B;
        // A: 128 rows x 4 chunks = 512 jobs
        #pragma unroll
        for (int i = 0; i < 2; i++) {
            int idx = tid + i * 256;
            int row = idx >> 2, c = idx & 3;
            cp_async16(st + sw_store(row, c), g_xh + (size_t)(m0 + row) * HDIM + kk + c * 8);
        }
        // G (64 rows) + U (64 rows): 512 jobs
        #pragma unroll
        for (int i = 0; i < 2; i++) {
            int idx = tid + i * 256;
            int up = idx >> 8;                 // 0: gate, 1: up
            int row = (idx & 255) >> 2, c = idx & 3;
            int feat = up ? (IDIM + n0 + row) : (n0 + row);
            char* dst = st + 8192 + up * 4096;
            cp_async16(dst + sw_store(row, c), Bbase + (size_t)feat * HDIM + kk + c * 8);
        }
    };

    #pragma unroll
    for (int s = 0; s < NSTAGE - 1; s++) { load_stage(s, s * 32); cp_commit(); }

    for (int it = 0; it < KITER; it++) {
        cp_wait<NSTAGE - 2>();
        __syncthreads();

        int nxt = it + NSTAGE - 1;
        if (nxt < KITER) load_stage(nxt % NSTAGE, nxt * 32);
        cp_commit();

        const char* A = smem + (it % NSTAGE) * STAGE_B;
        const char* G = A + 8192;
        const char* U = A + 12288;

        #pragma unroll
        for (int ks = 0; ks < 2; ks++) {
            int k0 = ks * 16;
            uint32_t a[2][4];
            #pragma unroll
            for (int mi = 0; mi < 2; mi++) {
                int R = wm * 32 + mi * 16;
                a[mi][0] = ld32_sw(A, R + g,     k0 + tg * 2);
                a[mi][1] = ld32_sw(A, R + g + 8, k0 + tg * 2);
                a[mi][2] = ld32_sw(A, R + g,     k0 + tg * 2 + 8);
                a[mi][3] = ld32_sw(A, R + g + 8, k0 + tg * 2 + 8);
            }
            #pragma unroll
            for (int ni = 0; ni < 4; ni++) {
                int col = wn * 32 + ni * 8 + g;
                uint32_t bg[2], bu[2];
                bg[0] = ld32_sw(G, col, k0 + tg * 2);
                bg[1] = ld32_sw(G, col, k0 + tg * 2 + 8);
                bu[0] = ld32_sw(U, col, k0 + tg * 2);
                bu[1] = ld32_sw(U, col, k0 + tg * 2 + 8);
                #pragma unroll
                for (int mi = 0; mi < 2; mi++) {
                    mma_f16(accG[mi][ni], a[mi], bg);
                    mma_f16(accU[mi][ni], a[mi], bu);
                }
            }
        }
    }

    // Epilogue: hid' = w * silu(gate) * up -> fp16
    #pragma unroll
    for (int mi = 0; mi < 2; mi++) {
        #pragma unroll
        for (int r2 = 0; r2 < 2; r2++) {
            int t = m0 + wm * 32 + mi * 16 + g + r2 * 8;
            float w = g_rw[t * TOPK + e];
            __half* dst = g_hid + (size_t)t * KC + (size_t)e * IDIM + n0;
            #pragma unroll
            for (int ni = 0; ni < 4; ni++) {
                int col = wn * 32 + ni * 8 + tg * 2;
                float gv0 = accG[mi][ni][r2 * 2 + 0], uv0 = accU[mi][ni][r2 * 2 + 0];
                float gv1 = accG[mi][ni][r2 * 2 + 1], uv1 = accU[mi][ni][r2 * 2 + 1];
                float h0 = (gv0 / (1.f + expf(-gv0))) * uv0 * w;
                float h1 = (gv1 / (1.f + expf(-gv1))) * uv1 * w;
                *(__half2*)(dst + col) = __floats2half2_rn(h0, h1);
            }
        }
    }
}

// ---------------------------------------------------------------------------
// GEMM2: out[4096,2048] = g_hid[4096,11264] @ down_flat[11264,2048]
// BM=128, BN=128, BK=32 halves. 8 warps (4x2), warp 32x64.
// ---------------------------------------------------------------------------
__global__ __launch_bounds__(256) void gemm2_kernel(float* __restrict__ OUT)
{
    __shared__ __align__(128) char smem[NSTAGE * STAGE_B];
    const int m0 = blockIdx.x * 128;
    const int n0 = blockIdx.y * 128;

    const int tid = threadIdx.x;
    const int wid = tid >> 5, lane = tid & 31;
    const int wm = wid & 3, wn = wid >> 2;
    const int g = lane >> 2, tg = lane & 3;

    float acc[2][8][4] = {};
    const int KITER = KC / 32;   // 352

    auto load_stage = [&](int s, int kk) {
        char* st = smem + s * STAGE_B;
        #pragma unroll
        for (int i = 0; i < 2; i++) {
            int idx = tid + i * 256;
            int row = idx >> 2, c = idx & 3;
            cp_async16(st + sw_store(row, c), g_hid + (size_t)(m0 + row) * KC + kk + c * 8);
        }
        #pragma unroll
        for (int i = 0; i < 2; i++) {
            int idx = tid + i * 256;
            int row = idx >> 2, c = idx & 3;
            cp_async16(st + 8192 + sw_store(row, c), g_dwh + (size_t)(n0 + row) * KC + kk + c * 8);
        }
    };

    #pragma unroll
    for (int s = 0; s < NSTAGE - 1; s++) { load_stage(s, s * 32); cp_commit(); }

    for (int it = 0; it < KITER; it++) {
        cp_wait<NSTAGE - 2>();
        __syncthreads();

        int nxt = it + NSTAGE - 1;
        if (nxt < KITER) load_stage(nxt % NSTAGE, nxt * 32);
        cp_commit();

        const char* A = smem + (it % NSTAGE) * STAGE_B;
        const char* B = A + 8192;

        #pragma unroll
        for (int ks = 0; ks < 2; ks++) {
            int k0 = ks * 16;
            uint32_t a[2][4];
            #pragma unroll
            for (int mi = 0; mi < 2; mi++) {
                int R = wm * 32 + mi * 16;
                a[mi][0] = ld32_sw(A, R + g,     k0 + tg * 2);
                a[mi][1] = ld32_sw(A, R + g + 8, k0 + tg * 2);
                a[mi][2] = ld32_sw(A, R + g,     k0 + tg * 2 + 8);
                a[mi][3] = ld32_sw(A, R + g + 8, k0 + tg * 2 + 8);
            }
            #pragma unroll
            for (int ni = 0; ni < 8; ni++) {
                int col = wn * 64 + ni * 8 + g;
                uint32_t b[2];
                b[0] = ld32_sw(B, col, k0 + tg * 2);
                b[1] = ld32_sw(B, col, k0 + tg * 2 + 8);
                #pragma unroll
                for (int mi = 0; mi < 2; mi++)
                    mma_f16(acc[mi][ni], a[mi], b);
            }
        }
    }

    #pragma unroll
    for (int mi = 0; mi < 2; mi++) {
        #pragma unroll
        for (int r2 = 0; r2 < 2; r2++) {
            int t = m0 + wm * 32 + mi * 16 + g + r2 * 8;
            #pragma unroll
            for (int ni = 0; ni < 8; ni++) {
                int col = n0 + wn * 64 + ni * 8 + tg * 2;
                float2 v;
                v.x = acc[mi][ni][r2 * 2 + 0];
                v.y = acc[mi][ni][r2 * 2 + 1];
                *(float2*)(OUT + (size_t)t * HDIM + col) = v;
            }
        }
    }
}

// ---------------------------------------------------------------------------
extern "C" void kernel_launch(void* const* d_in, const int* in_sizes, int n_in,
                              void* d_out, int out_size) {
    const float* x  = (const float*)d_in[0];
    const float* rw = (const float*)d_in[1];
    const float* gu = (const float*)d_in[2];
    const float* dw = (const float*)d_in[3];
    float* out = (float*)d_out;

    const long long OUT_ELEMS = (long long)T_TOK * HDIM;
    float* tail = nullptr;
    if ((long long)out_size >= OUT_ELEMS + (long long)T_TOK * TOPK)
        tail = out + OUT_ELEMS;

    cvt_x_kernel<<<2048, 256>>>(x);
    tpose_gu_kernel<<<dim3(TWOI / 32, HDIM / 32, TOPK), dim3(32, 8)>>>(gu);
    tpose_dw_kernel<<<dim3(IDIM / 32, HDIM / 32, TOPK), dim3(32, 8)>>>(dw);
    router_kernel<<<T_TOK / 8, 256>>>(x, rw, tail);

    dim3 grid1(T_TOK / 128, IDIM / 64, TOPK);   // (32, 22, 8)
    gemm1_kernel<<<grid1, 256>>>();

    dim3 grid2(T_TOK / 128, HDIM / 128);        // (32, 16)
    gemm2_kernel<<<grid2, 256>>>(out);
}

// round 6
// speedup vs baseline: 2.3638x; 1.0136x over previous
#include <cuda_runtime.h>
#include <cuda_fp16.h>
#include <cstdint>

// Fixed shapes for NKIMoELayer_24970939859026
#define T_TOK 4096
#define HDIM  2048
#define NEXP  16
#define TOPK  8             // reference uses experts 0..7 densely
#define IDIM  1408
#define TWOI  2816
#define KC    (TOPK * IDIM) // 11264

// Scratch (__device__ globals: allocation-free rule)
__device__ __half g_hid[(size_t)T_TOK * KC];          // hid' fp16       [t][e*IDIM+i]
__device__ float  g_rw [T_TOK * TOPK];
__device__ __half g_xh [(size_t)T_TOK * HDIM];        // fp16(X)         [t][h]
__device__ __half g_guh[(size_t)TOPK * TWOI * HDIM];  // fp16(gate_up^T) [e][feat][h]
__device__ __half g_dwh[(size_t)HDIM * KC];           // fp16(down^T)    [n][k]

__device__ __forceinline__ void mma_f16(float* c, const uint32_t* a, uint32_t b0, uint32_t b1) {
    asm volatile(
        "mma.sync.aligned.m16n8k16.row.col.f32.f16.f16.f32 "
        "{%0,%1,%2,%3}, {%4,%5,%6,%7}, {%8,%9}, {%0,%1,%2,%3};"
        : "+f"(c[0]), "+f"(c[1]), "+f"(c[2]), "+f"(c[3])
        : "r"(a[0]), "r"(a[1]), "r"(a[2]), "r"(a[3]), "r"(b0), "r"(b1));
}

__device__ __forceinline__ void ldsm4(uint32_t* r, uint32_t addr) {
    asm volatile("ldmatrix.sync.aligned.m8n8.x4.shared.b16 {%0,%1,%2,%3}, [%4];"
        : "=r"(r[0]), "=r"(r[1]), "=r"(r[2]), "=r"(r[3]) : "r"(addr));
}

__device__ __forceinline__ void cp_async16(void* smem, const void* gmem) {
    uint32_t s = (uint32_t)__cvta_generic_to_shared(smem);
    asm volatile("cp.async.cg.shared.global [%0], [%1], 16;" :: "r"(s), "l"(gmem));
}
__device__ __forceinline__ void cp_commit() { asm volatile("cp.async.commit_group;"); }
template<int N> __device__ __forceinline__ void cp_wait() {
    asm volatile("cp.async.wait_group %0;" :: "n"(N));
}

// XOR-swizzled tile: row stride 64B (32 halves), 4 chunks of 16B per row.
// Stored chunk position = c ^ ((row>>1)&3).
__device__ __forceinline__ uint32_t sw_store(int row, int c) {
    return (uint32_t)(row * 64 + ((c ^ ((row >> 1) & 3)) << 4));
}
// ldmatrix lane address for a 16x16 fragment group at (rowbase, kchunk base)
// lane mapping: lr = lane&7 (row within 8), hm = (lane>>3)&1 (row half),
// hk = lane>>4 (k half / chunk +0/+1).
__device__ __forceinline__ uint32_t ldsm_addr(uint32_t tilebase, int rowbase, int cbase,
                                              int lr, int hm, int hk) {
    int row = rowbase + hm * 8 + lr;
    return tilebase + (uint32_t)(row * 64) + (uint32_t)((((cbase + hk) ^ ((row >> 1) & 3)) << 4));
}

// ---------------------------------------------------------------------------
// Pre-pass: fp32 -> fp16 convert / transpose
// ---------------------------------------------------------------------------
__global__ __launch_bounds__(256) void cvt_x_kernel(const float* __restrict__ src) {
    const long long n4 = (long long)T_TOK * HDIM / 4;
    long long i = (long long)blockIdx.x * blockDim.x + threadIdx.x;
    long long st = (long long)gridDim.x * blockDim.x;
    for (; i < n4; i += st) {
        float4 v = ((const float4*)src)[i];
        ((__half2*)g_xh)[i * 2 + 0] = __floats2half2_rn(v.x, v.y);
        ((__half2*)g_xh)[i * 2 + 1] = __floats2half2_rn(v.z, v.w);
    }
}
// gate_up[e][h][n] -> g_guh[e][n][h]
__global__ __launch_bounds__(256) void tpose_gu_kernel(const float* __restrict__ src) {
    __shared__ float tile[32][33];
    int e = blockIdx.z, n0 = blockIdx.x * 32, h0 = blockIdx.y * 32;
    int tx = threadIdx.x, ty = threadIdx.y;
    #pragma unroll
    for (int r = ty; r < 32; r += 8)
        tile[r][tx] = src[((size_t)e * HDIM + h0 + r) * TWOI + n0 + tx];
    __syncthreads();
    #pragma unroll
    for (int r = ty; r < 32; r += 8)
        g_guh[((size_t)e * TWOI + n0 + r) * HDIM + h0 + tx] = __float2half_rn(tile[tx][r]);
}
// down[e][i][h] -> g_dwh[h][e*IDIM+i]
__global__ __launch_bounds__(256) void tpose_dw_kernel(const float* __restrict__ src) {
    __shared__ float tile[32][33];
    int e = blockIdx.z, i0 = blockIdx.x * 32, h0 = blockIdx.y * 32;
    int tx = threadIdx.x, ty = threadIdx.y;
    #pragma unroll
    for (int r = ty; r < 32; r += 8)
        tile[r][tx] = src[((size_t)e * IDIM + i0 + r) * HDIM + h0 + tx];
    __syncthreads();
    #pragma unroll
    for (int r = ty; r < 32; r += 8)
        g_dwh[(size_t)(h0 + r) * KC + (size_t)e * IDIM + i0 + tx] = __float2half_rn(tile[tx][r]);
}

// ---------------------------------------------------------------------------
// Router: one warp per token
// ---------------------------------------------------------------------------
__global__ __launch_bounds__(256) void router_kernel(
    const float* __restrict__ x, const float* __restrict__ rw, float* __restrict__ w_tail)
{
    int t = (blockIdx.x * blockDim.x + threadIdx.x) >> 5;
    int lane = threadIdx.x & 31;
    if (t >= T_TOK) return;
    const float* xr = x + (size_t)t * HDIM;
    float acc[NEXP] = {};
    for (int h = lane; h < HDIM; h += 32) {
        float xv = xr[h];
        const float4* r4 = (const float4*)(rw + (size_t)h * NEXP);
        float4 a = r4[0], b = r4[1], c = r4[2], d = r4[3];
        acc[0]+=xv*a.x; acc[1]+=xv*a.y; acc[2]+=xv*a.z; acc[3]+=xv*a.w;
        acc[4]+=xv*b.x; acc[5]+=xv*b.y; acc[6]+=xv*b.z; acc[7]+=xv*b.w;
        acc[8]+=xv*c.x; acc[9]+=xv*c.y; acc[10]+=xv*c.z; acc[11]+=xv*c.w;
        acc[12]+=xv*d.x; acc[13]+=xv*d.y; acc[14]+=xv*d.z; acc[15]+=xv*d.w;
    }
    #pragma unroll
    for (int e = 0; e < NEXP; e++) {
        #pragma unroll
        for (int o = 16; o; o >>= 1) acc[e] += __shfl_xor_sync(0xFFFFFFFFu, acc[e], o);
    }
    if (lane == 0) {
        float m = acc[0];
        #pragma unroll
        for (int e = 1; e < NEXP; e++) m = fmaxf(m, acc[e]);
        float p[NEXP];
        #pragma unroll
        for (int e = 0; e < NEXP; e++) p[e] = expf(acc[e] - m);
        float v[TOPK]; float ssel = 0.f;
        #pragma unroll
        for (int k = 0; k < TOPK; k++) {
            int bi = 0; float bv = -1.f;
            #pragma unroll
            for (int e = 0; e < NEXP; e++) if (p[e] > bv) { bv = p[e]; bi = e; }
            p[bi] = -2.f; v[k] = bv; ssel += bv;
        }
        float inv = 1.f / ssel;
        #pragma unroll
        for (int k = 0; k < TOPK; k++) {
            float wv = v[k] * inv;
            g_rw[t * TOPK + k] = wv;
            if (w_tail) w_tail[t * TOPK + k] = wv;
        }
    }
}

#define NSTAGE 3
#define STAGE_B 16384   // A tile 8 KB (128 rows x 64B) + B region 8 KB

// ---------------------------------------------------------------------------
// GEMM1: hid'[t, e*IDIM+n] = w[t,e] * silu(X@GUe[:,n]) * (X@GUe[:,IDIM+n])
// BM=128, BN=64(gate)+64(up), BK=32 halves. 8 warps (4x2), warp 32x32(+32x32).
// ---------------------------------------------------------------------------
__global__ __launch_bounds__(256) void gemm1_kernel()
{
    __shared__ __align__(128) char smem[NSTAGE * STAGE_B];
    const uint32_t sbase = (uint32_t)__cvta_generic_to_shared(smem);
    const int m0 = blockIdx.x * 128;
    const int n0 = blockIdx.y * 64;
    const int e  = blockIdx.z;
    const __half* Bbase = g_guh + (size_t)e * TWOI * HDIM;

    const int tid = threadIdx.x;
    const int wid = tid >> 5, lane = tid & 31;
    const int wm = wid & 3, wn = wid >> 2;
    const int g = lane >> 2, tg = lane & 3;
    const int lr = lane & 7, hm = (lane >> 3) & 1, hk = lane >> 4;

    float accG[2][4][4] = {};
    float accU[2][4][4] = {};
    const int KITER = HDIM / 32;   // 64

    auto load_stage = [&](int s, int kk) {
        char* st = smem + s * STAGE_B;
        #pragma unroll
        for (int i = 0; i < 2; i++) {
            int idx = tid + i * 256;
            int row = idx >> 2, c = idx & 3;
            cp_async16(st + sw_store(row, c), g_xh + (size_t)(m0 + row) * HDIM + kk + c * 8);
        }
        #pragma unroll
        for (int i = 0; i < 2; i++) {
            int idx = tid + i * 256;
            int up = idx >> 8;                 // 0: gate, 1: up
            int row = (idx & 255) >> 2, c = idx & 3;
            int feat = up ? (IDIM + n0 + row) : (n0 + row);
            char* dst = st + 8192 + up * 4096;
            cp_async16(dst + sw_store(row, c), Bbase + (size_t)feat * HDIM + kk + c * 8);
        }
    };

    #pragma unroll
    for (int s = 0; s < NSTAGE - 1; s++) { load_stage(s, s * 32); cp_commit(); }

    for (int it = 0; it < KITER; it++) {
        cp_wait<NSTAGE - 2>();
        __syncthreads();

        int nxt = it + NSTAGE - 1;
        if (nxt < KITER) load_stage(nxt % NSTAGE, nxt * 32);
        cp_commit();

        const uint32_t At = sbase + (uint32_t)((it % NSTAGE) * STAGE_B);
        const uint32_t Gt = At + 8192;
        const uint32_t Ut = At + 12288;

        #pragma unroll
        for (int ks = 0; ks < 2; ks++) {
            int cb = ks * 2;                      // k-chunk base (k0 = ks*16)
            uint32_t a[2][4];
            #pragma unroll
            for (int mi = 0; mi < 2; mi++)
                ldsm4(a[mi], ldsm_addr(At, wm * 32 + mi * 16, cb, lr, hm, hk));
            uint32_t bg[2][4], bu[2][4];
            #pragma unroll
            for (int p = 0; p < 2; p++) {
                ldsm4(bg[p], ldsm_addr(Gt, wn * 32 + p * 16, cb, lr, hm, hk));
                ldsm4(bu[p], ldsm_addr(Ut, wn * 32 + p * 16, cb, lr, hm, hk));
            }
            #pragma unroll
            for (int ni = 0; ni < 4; ni++) {
                int p = ni >> 1, o = ni & 1;
                #pragma unroll
                for (int mi = 0; mi < 2; mi++) {
                    mma_f16(accG[mi][ni], a[mi], bg[p][o], bg[p][o + 2]);
                    mma_f16(accU[mi][ni], a[mi], bu[p][o], bu[p][o + 2]);
                }
            }
        }
    }

    // Epilogue: hid' = w * silu(gate) * up -> fp16
    #pragma unroll
    for (int mi = 0; mi < 2; mi++) {
        #pragma unroll
        for (int r2 = 0; r2 < 2; r2++) {
            int t = m0 + wm * 32 + mi * 16 + g + r2 * 8;
            float w = g_rw[t * TOPK + e];
            __half* dst = g_hid + (size_t)t * KC + (size_t)e * IDIM + n0;
            #pragma unroll
            for (int ni = 0; ni < 4; ni++) {
                int col = wn * 32 + ni * 8 + tg * 2;
                float gv0 = accG[mi][ni][r2 * 2 + 0], uv0 = accU[mi][ni][r2 * 2 + 0];
                float gv1 = accG[mi][ni][r2 * 2 + 1], uv1 = accU[mi][ni][r2 * 2 + 1];
                float h0 = (gv0 / (1.f + expf(-gv0))) * uv0 * w;
                float h1 = (gv1 / (1.f + expf(-gv1))) * uv1 * w;
                *(__half2*)(dst + col) = __floats2half2_rn(h0, h1);
            }
        }
    }
}

// ---------------------------------------------------------------------------
// GEMM2: out[4096,2048] = g_hid[4096,11264] @ down_flat[11264,2048]
// BM=128, BN=128, BK=32 halves. 8 warps (4x2), warp 32x64.
// ---------------------------------------------------------------------------
__global__ __launch_bounds__(256) void gemm2_kernel(float* __restrict__ OUT)
{
    __shared__ __align__(128) char smem[NSTAGE * STAGE_B];
    const uint32_t sbase = (uint32_t)__cvta_generic_to_shared(smem);
    const int m0 = blockIdx.x * 128;
    const int n0 = blockIdx.y * 128;

    const int tid = threadIdx.x;
    const int wid = tid >> 5, lane = tid & 31;
    const int wm = wid & 3, wn = wid >> 2;
    const int g = lane >> 2, tg = lane & 3;
    const int lr = lane & 7, hm = (lane >> 3) & 1, hk = lane >> 4;

    float acc[2][8][4] = {};
    const int KITER = KC / 32;   // 352

    auto load_stage = [&](int s, int kk) {
        char* st = smem + s * STAGE_B;
        #pragma unroll
        for (int i = 0; i < 2; i++) {
            int idx = tid + i * 256;
            int row = idx >> 2, c = idx & 3;
            cp_async16(st + sw_store(row, c), g_hid + (size_t)(m0 + row) * KC + kk + c * 8);
        }
        #pragma unroll
        for (int i = 0; i < 2; i++) {
            int idx = tid + i * 256;
            int row = idx >> 2, c = idx & 3;
            cp_async16(st + 8192 + sw_store(row, c), g_dwh + (size_t)(n0 + row) * KC + kk + c * 8);
        }
    };

    #pragma unroll
    for (int s = 0; s < NSTAGE - 1; s++) { load_stage(s, s * 32); cp_commit(); }

    for (int it = 0; it < KITER; it++) {
        cp_wait<NSTAGE - 2>();
        __syncthreads();

        int nxt = it + NSTAGE - 1;
        if (nxt < KITER) load_stage(nxt % NSTAGE, nxt * 32);
        cp_commit();

        const uint32_t At = sbase + (uint32_t)((it % NSTAGE) * STAGE_B);
        const uint32_t Bt = At + 8192;

        #pragma unroll
        for (int ks = 0; ks < 2; ks++) {
            int cb = ks * 2;
            uint32_t a[2][4];
            #pragma unroll
            for (int mi = 0; mi < 2; mi++)
                ldsm4(a[mi], ldsm_addr(At, wm * 32 + mi * 16, cb, lr, hm, hk));
            uint32_t b[4][4];
            #pragma unroll
            for (int p = 0; p < 4; p++)
                ldsm4(b[p], ldsm_addr(Bt, wn * 64 + p * 16, cb, lr, hm, hk));
            #pragma unroll
            for (int ni = 0; ni < 8; ni++) {
                int p = ni >> 1, o = ni & 1;
                #pragma unroll
                for (int mi = 0; mi < 2; mi++)
                    mma_f16(acc[mi][ni], a[mi], b[p][o], b[p][o + 2]);
            }
        }
    }

    #pragma unroll
    for (int mi = 0; mi < 2; mi++) {
        #pragma unroll
        for (int r2 = 0; r2 < 2; r2++) {
            int t = m0 + wm * 32 + mi * 16 + g + r2 * 8;
            #pragma unroll
            for (int ni = 0; ni < 8; ni++) {
                int col = n0 + wn * 64 + ni * 8 + tg * 2;
                float2 v;
                v.x = acc[mi][ni][r2 * 2 + 0];
                v.y = acc[mi][ni][r2 * 2 + 1];
                *(float2*)(OUT + (size_t)t * HDIM + col) = v;
            }
        }
    }
}

// ---------------------------------------------------------------------------
extern "C" void kernel_launch(void* const* d_in, const int* in_sizes, int n_in,
                              void* d_out, int out_size) {
    const float* x  = (const float*)d_in[0];
    const float* rw = (const float*)d_in[1];
    const float* gu = (const float*)d_in[2];
    const float* dw = (const float*)d_in[3];
    float* out = (float*)d_out;

    const long long OUT_ELEMS = (long long)T_TOK * HDIM;
    float* tail = nullptr;
    if ((long long)out_size >= OUT_ELEMS + (long long)T_TOK * TOPK)
        tail = out + OUT_ELEMS;

    cvt_x_kernel<<<2048, 256>>>(x);
    tpose_gu_kernel<<<dim3(TWOI / 32, HDIM / 32, TOPK), dim3(32, 8)>>>(gu);
    tpose_dw_kernel<<<dim3(IDIM / 32, HDIM / 32, TOPK), dim3(32, 8)>>>(dw);
    router_kernel<<<T_TOK / 8, 256>>>(x, rw, tail);

    dim3 grid1(T_TOK / 128, IDIM / 64, TOPK);   // (32, 22, 8)
    gemm1_kernel<<<grid1, 256>>>();

    dim3 grid2(T_TOK / 128, HDIM / 128);        // (32, 16)
    gemm2_kernel<<<grid2, 256>>>(out);
}

// round 7
// speedup vs baseline: 2.6581x; 1.1245x over previous
#include <cuda_runtime.h>
#include <cuda_fp16.h>
#include <cstdint>

// Fixed shapes for NKIMoELayer_24970939859026
#define T_TOK 4096
#define HDIM  2048
#define NEXP  16
#define TOPK  8             // reference uses experts 0..7 densely
#define IDIM  1408
#define TWOI  2816
#define KC    (TOPK * IDIM) // 11264

// Scratch (__device__ globals: allocation-free rule)
__device__ __half g_hid[(size_t)T_TOK * KC];          // hid' fp16       [t][e*IDIM+i]
__device__ float  g_rw [T_TOK * TOPK];
__device__ __half g_xh [(size_t)T_TOK * HDIM];        // fp16(X)         [t][h]
__device__ __half g_guh[(size_t)TOPK * TWOI * HDIM];  // fp16(gate_up^T) [e][feat][h]
__device__ __half g_dwh[(size_t)HDIM * KC];           // fp16(down^T)    [n][k]

__device__ __forceinline__ void mma_f16(float* c, const uint32_t* a, uint32_t b0, uint32_t b1) {
    asm volatile(
        "mma.sync.aligned.m16n8k16.row.col.f32.f16.f16.f32 "
        "{%0,%1,%2,%3}, {%4,%5,%6,%7}, {%8,%9}, {%0,%1,%2,%3};"
        : "+f"(c[0]), "+f"(c[1]), "+f"(c[2]), "+f"(c[3])
        : "r"(a[0]), "r"(a[1]), "r"(a[2]), "r"(a[3]), "r"(b0), "r"(b1));
}

__device__ __forceinline__ void ldsm4(uint32_t* r, uint32_t addr) {
    asm volatile("ldmatrix.sync.aligned.m8n8.x4.shared.b16 {%0,%1,%2,%3}, [%4];"
        : "=r"(r[0]), "=r"(r[1]), "=r"(r[2]), "=r"(r[3]) : "r"(addr));
}

__device__ __forceinline__ void cp_async16(uint32_t smem, const void* gmem) {
    asm volatile("cp.async.cg.shared.global [%0], [%1], 16;" :: "r"(smem), "l"(gmem));
}
__device__ __forceinline__ void cp_commit() { asm volatile("cp.async.commit_group;"); }
template<int N> __device__ __forceinline__ void cp_wait() {
    asm volatile("cp.async.wait_group %0;" :: "n"(N));
}

// SW128 swizzled tile, BK=64 halves: row stride 128B, 8 chunks of 16B/row.
// chunk position = c ^ (row & 7).
__device__ __forceinline__ uint32_t sw_store(int row, int c) {
    return (uint32_t)(row * 128 + ((c ^ (row & 7)) << 4));
}
// ldmatrix lane address: lr = lane&7, hm = (lane>>3)&1 (row half),
// hk = lane>>4 (k chunk +0/+1), cb = even chunk base (k0 = cb*8).
__device__ __forceinline__ uint32_t ldsm_addr(uint32_t tilebase, int rowbase, int cb,
                                              int lr, int hm, int hk) {
    int row = rowbase + hm * 8 + lr;
    return tilebase + (uint32_t)(row * 128) + (uint32_t)((((cb + hk) ^ (row & 7)) << 4));
}

// ---------------------------------------------------------------------------
// Pre-pass: fp32 -> fp16 convert / transpose
// ---------------------------------------------------------------------------
__global__ __launch_bounds__(256) void cvt_x_kernel(const float* __restrict__ src) {
    const long long n4 = (long long)T_TOK * HDIM / 4;
    long long i = (long long)blockIdx.x * blockDim.x + threadIdx.x;
    long long st = (long long)gridDim.x * blockDim.x;
    for (; i < n4; i += st) {
        float4 v = ((const float4*)src)[i];
        ((__half2*)g_xh)[i * 2 + 0] = __floats2half2_rn(v.x, v.y);
        ((__half2*)g_xh)[i * 2 + 1] = __floats2half2_rn(v.z, v.w);
    }
}
// gate_up[e][h][n] -> g_guh[e][n][h]
__global__ __launch_bounds__(256) void tpose_gu_kernel(const float* __restrict__ src) {
    __shared__ float tile[32][33];
    int e = blockIdx.z, n0 = blockIdx.x * 32, h0 = blockIdx.y * 32;
    int tx = threadIdx.x, ty = threadIdx.y;
    #pragma unroll
    for (int r = ty; r < 32; r += 8)
        tile[r][tx] = src[((size_t)e * HDIM + h0 + r) * TWOI + n0 + tx];
    __syncthreads();
    #pragma unroll
    for (int r = ty; r < 32; r += 8)
        g_guh[((size_t)e * TWOI + n0 + r) * HDIM + h0 + tx] = __float2half_rn(tile[tx][r]);
}
// down[e][i][h] -> g_dwh[h][e*IDIM+i]
__global__ __launch_bounds__(256) void tpose_dw_kernel(const float* __restrict__ src) {
    __shared__ float tile[32][33];
    int e = blockIdx.z, i0 = blockIdx.x * 32, h0 = blockIdx.y * 32;
    int tx = threadIdx.x, ty = threadIdx.y;
    #pragma unroll
    for (int r = ty; r < 32; r += 8)
        tile[r][tx] = src[((size_t)e * IDIM + i0 + r) * HDIM + h0 + tx];
    __syncthreads();
    #pragma unroll
    for (int r = ty; r < 32; r += 8)
        g_dwh[(size_t)(h0 + r) * KC + (size_t)e * IDIM + i0 + tx] = __float2half_rn(tile[tx][r]);
}

// ---------------------------------------------------------------------------
// Router: one warp per token
// ---------------------------------------------------------------------------
__global__ __launch_bounds__(256) void router_kernel(
    const float* __restrict__ x, const float* __restrict__ rw, float* __restrict__ w_tail)
{
    int t = (blockIdx.x * blockDim.x + threadIdx.x) >> 5;
    int lane = threadIdx.x & 31;
    if (t >= T_TOK) return;
    const float* xr = x + (size_t)t * HDIM;
    float acc[NEXP] = {};
    for (int h = lane; h < HDIM; h += 32) {
        float xv = xr[h];
        const float4* r4 = (const float4*)(rw + (size_t)h * NEXP);
        float4 a = r4[0], b = r4[1], c = r4[2], d = r4[3];
        acc[0]+=xv*a.x; acc[1]+=xv*a.y; acc[2]+=xv*a.z; acc[3]+=xv*a.w;
        acc[4]+=xv*b.x; acc[5]+=xv*b.y; acc[6]+=xv*b.z; acc[7]+=xv*b.w;
        acc[8]+=xv*c.x; acc[9]+=xv*c.y; acc[10]+=xv*c.z; acc[11]+=xv*c.w;
        acc[12]+=xv*d.x; acc[13]+=xv*d.y; acc[14]+=xv*d.z; acc[15]+=xv*d.w;
    }
    #pragma unroll
    for (int e = 0; e < NEXP; e++) {
        #pragma unroll
        for (int o = 16; o; o >>= 1) acc[e] += __shfl_xor_sync(0xFFFFFFFFu, acc[e], o);
    }
    if (lane == 0) {
        float m = acc[0];
        #pragma unroll
        for (int e = 1; e < NEXP; e++) m = fmaxf(m, acc[e]);
        float p[NEXP];
        #pragma unroll
        for (int e = 0; e < NEXP; e++) p[e] = expf(acc[e] - m);
        float v[TOPK]; float ssel = 0.f;
        #pragma unroll
        for (int k = 0; k < TOPK; k++) {
            int bi = 0; float bv = -1.f;
            #pragma unroll
            for (int e = 0; e < NEXP; e++) if (p[e] > bv) { bv = p[e]; bi = e; }
            p[bi] = -2.f; v[k] = bv; ssel += bv;
        }
        float inv = 1.f / ssel;
        #pragma unroll
        for (int k = 0; k < TOPK; k++) {
            float wv = v[k] * inv;
            g_rw[t * TOPK + k] = wv;
            if (w_tail) w_tail[t * TOPK + k] = wv;
        }
    }
}

#define NSTAGE  3
#define STAGE_B 32768    // A tile 16 KB (128 rows x 128B) + B region 16 KB
#define G_SMEM  (NSTAGE * STAGE_B)

// ---------------------------------------------------------------------------
// GEMM1: hid'[t, e*IDIM+n] = w[t,e] * silu(X@GUe[:,n]) * (X@GUe[:,IDIM+n])
// BM=128, BN=64(gate)+64(up), BK=64 halves. 8 warps (4x2), warp 32x32(+32x32).
// ---------------------------------------------------------------------------
__global__ __launch_bounds__(256, 2) void gemm1_kernel()
{
    extern __shared__ __align__(128) char smem[];
    const uint32_t sbase = (uint32_t)__cvta_generic_to_shared(smem);
    const int m0 = blockIdx.x * 128;
    const int n0 = blockIdx.y * 64;
    const int e  = blockIdx.z;
    const __half* Bbase = g_guh + (size_t)e * TWOI * HDIM;

    const int tid = threadIdx.x;
    const int wid = tid >> 5, lane = tid & 31;
    const int wm = wid & 3, wn = wid >> 2;
    const int g = lane >> 2, tg = lane & 3;
    const int lr = lane & 7, hm = (lane >> 3) & 1, hk = lane >> 4;

    float accG[2][4][4] = {};
    float accU[2][4][4] = {};
    const int KITER = HDIM / 64;   // 32

    auto load_stage = [&](int s, int kk) {
        uint32_t st = sbase + (uint32_t)(s * STAGE_B);
        // A: 128 rows x 8 chunks = 1024 jobs -> 4/thread
        #pragma unroll
        for (int i = 0; i < 4; i++) {
            int idx = tid + i * 256;
            int row = idx >> 3, c = idx & 7;
            cp_async16(st + sw_store(row, c), g_xh + (size_t)(m0 + row) * HDIM + kk + c * 8);
        }
        // G (64 rows) + U (64 rows): 1024 jobs -> 4/thread
        #pragma unroll
        for (int i = 0; i < 4; i++) {
            int idx = tid + i * 256;
            int up = idx >> 9;                 // 0: gate, 1: up
            int row = (idx & 511) >> 3, c = idx & 7;
            int feat = up ? (IDIM + n0 + row) : (n0 + row);
            uint32_t dst = st + 16384 + (uint32_t)(up * 8192);
            cp_async16(dst + sw_store(row, c), Bbase + (size_t)feat * HDIM + kk + c * 8);
        }
    };

    #pragma unroll
    for (int s = 0; s < NSTAGE - 1; s++) { load_stage(s, s * 64); cp_commit(); }

    for (int it = 0; it < KITER; it++) {
        cp_wait<NSTAGE - 2>();
        __syncthreads();

        int nxt = it + NSTAGE - 1;
        if (nxt < KITER) load_stage(nxt % NSTAGE, nxt * 64);
        cp_commit();

        const uint32_t At = sbase + (uint32_t)((it % NSTAGE) * STAGE_B);
        const uint32_t Gt = At + 16384;
        const uint32_t Ut = At + 24576;

        #pragma unroll
        for (int ks = 0; ks < 4; ks++) {
            int cb = ks * 2;                      // k0 = ks*16
            uint32_t a[2][4];
            #pragma unroll
            for (int mi = 0; mi < 2; mi++)
                ldsm4(a[mi], ldsm_addr(At, wm * 32 + mi * 16, cb, lr, hm, hk));
            uint32_t bg[2][4], bu[2][4];
            #pragma unroll
            for (int p = 0; p < 2; p++) {
                ldsm4(bg[p], ldsm_addr(Gt, wn * 32 + p * 16, cb, lr, hm, hk));
                ldsm4(bu[p], ldsm_addr(Ut, wn * 32 + p * 16, cb, lr, hm, hk));
            }
            #pragma unroll
            for (int ni = 0; ni < 4; ni++) {
                int p = ni >> 1, o = ni & 1;
                #pragma unroll
                for (int mi = 0; mi < 2; mi++) {
                    mma_f16(accG[mi][ni], a[mi], bg[p][o], bg[p][o + 2]);
                    mma_f16(accU[mi][ni], a[mi], bu[p][o], bu[p][o + 2]);
                }
            }
        }
    }

    // Epilogue: hid' = w * silu(gate) * up -> fp16
    #pragma unroll
    for (int mi = 0; mi < 2; mi++) {
        #pragma unroll
        for (int r2 = 0; r2 < 2; r2++) {
            int t = m0 + wm * 32 + mi * 16 + g + r2 * 8;
            float w = g_rw[t * TOPK + e];
            __half* dst = g_hid + (size_t)t * KC + (size_t)e * IDIM + n0;
            #pragma unroll
            for (int ni = 0; ni < 4; ni++) {
                int col = wn * 32 + ni * 8 + tg * 2;
                float gv0 = accG[mi][ni][r2 * 2 + 0], uv0 = accU[mi][ni][r2 * 2 + 0];
                float gv1 = accG[mi][ni][r2 * 2 + 1], uv1 = accU[mi][ni][r2 * 2 + 1];
                float h0 = (gv0 / (1.f + expf(-gv0))) * uv0 * w;
                float h1 = (gv1 / (1.f + expf(-gv1))) * uv1 * w;
                *(__half2*)(dst + col) = __floats2half2_rn(h0, h1);
            }
        }
    }
}

// ---------------------------------------------------------------------------
// GEMM2: out[4096,2048] = g_hid[4096,11264] @ down_flat[11264,2048]
// BM=128, BN=128, BK=64 halves. 8 warps (4x2), warp 32x64.
// ---------------------------------------------------------------------------
__global__ __launch_bounds__(256, 2) void gemm2_kernel(float* __restrict__ OUT)
{
    extern __shared__ __align__(128) char smem[];
    const uint32_t sbase = (uint32_t)__cvta_generic_to_shared(smem);
    const int m0 = blockIdx.x * 128;
    const int n0 = blockIdx.y * 128;

    const int tid = threadIdx.x;
    const int wid = tid >> 5, lane = tid & 31;
    const int wm = wid & 3, wn = wid >> 2;
    const int g = lane >> 2, tg = lane & 3;
    const int lr = lane & 7, hm = (lane >> 3) & 1, hk = lane >> 4;

    float acc[2][8][4] = {};
    const int KITER = KC / 64;   // 176

    auto load_stage = [&](int s, int kk) {
        uint32_t st = sbase + (uint32_t)(s * STAGE_B);
        #pragma unroll
        for (int i = 0; i < 4; i++) {
            int idx = tid + i * 256;
            int row = idx >> 3, c = idx & 7;
            cp_async16(st + sw_store(row, c), g_hid + (size_t)(m0 + row) * KC + kk + c * 8);
        }
        #pragma unroll
        for (int i = 0; i < 4; i++) {
            int idx = tid + i * 256;
            int row = idx >> 3, c = idx & 7;
            cp_async16(st + 16384 + sw_store(row, c), g_dwh + (size_t)(n0 + row) * KC + kk + c * 8);
        }
    };

    #pragma unroll
    for (int s = 0; s < NSTAGE - 1; s++) { load_stage(s, s * 64); cp_commit(); }

    for (int it = 0; it < KITER; it++) {
        cp_wait<NSTAGE - 2>();
        __syncthreads();

        int nxt = it + NSTAGE - 1;
        if (nxt < KITER) load_stage(nxt % NSTAGE, nxt * 64);
        cp_commit();

        const uint32_t At = sbase + (uint32_t)((it % NSTAGE) * STAGE_B);
        const uint32_t Bt = At + 16384;

        #pragma unroll
        for (int ks = 0; ks < 4; ks++) {
            int cb = ks * 2;
            uint32_t a[2][4];
            #pragma unroll
            for (int mi = 0; mi < 2; mi++)
                ldsm4(a[mi], ldsm_addr(At, wm * 32 + mi * 16, cb, lr, hm, hk));
            uint32_t b[4][4];
            #pragma unroll
            for (int p = 0; p < 4; p++)
                ldsm4(b[p], ldsm_addr(Bt, wn * 64 + p * 16, cb, lr, hm, hk));
            #pragma unroll
            for (int ni = 0; ni < 8; ni++) {
                int p = ni >> 1, o = ni & 1;
                #pragma unroll
                for (int mi = 0; mi < 2; mi++)
                    mma_f16(acc[mi][ni], a[mi], b[p][o], b[p][o + 2]);
            }
        }
    }

    #pragma unroll
    for (int mi = 0; mi < 2; mi++) {
        #pragma unroll
        for (int r2 = 0; r2 < 2; r2++) {
            int t = m0 + wm * 32 + mi * 16 + g + r2 * 8;
            #pragma unroll
            for (int ni = 0; ni < 8; ni++) {
                int col = n0 + wn * 64 + ni * 8 + tg * 2;
                float2 v;
                v.x = acc[mi][ni][r2 * 2 + 0];
                v.y = acc[mi][ni][r2 * 2 + 1];
                *(float2*)(OUT + (size_t)t * HDIM + col) = v;
            }
        }
    }
}

// ---------------------------------------------------------------------------
extern "C" void kernel_launch(void* const* d_in, const int* in_sizes, int n_in,
                              void* d_out, int out_size) {
    const float* x  = (const float*)d_in[0];
    const float* rw = (const float*)d_in[1];
    const float* gu = (const float*)d_in[2];
    const float* dw = (const float*)d_in[3];
    float* out = (float*)d_out;

    const long long OUT_ELEMS = (long long)T_TOK * HDIM;
    float* tail = nullptr;
    if ((long long)out_size >= OUT_ELEMS + (long long)T_TOK * TOPK)
        tail = out + OUT_ELEMS;

    cudaFuncSetAttribute(gemm1_kernel, cudaFuncAttributeMaxDynamicSharedMemorySize, G_SMEM);
    cudaFuncSetAttribute(gemm2_kernel, cudaFuncAttributeMaxDynamicSharedMemorySize, G_SMEM);

    cvt_x_kernel<<<2048, 256>>>(x);
    tpose_gu_kernel<<<dim3(TWOI / 32, HDIM / 32, TOPK), dim3(32, 8)>>>(gu);
    tpose_dw_kernel<<<dim3(IDIM / 32, HDIM / 32, TOPK), dim3(32, 8)>>>(dw);
    router_kernel<<<T_TOK / 8, 256>>>(x, rw, tail);

    dim3 grid1(T_TOK / 128, IDIM / 64, TOPK);   // (32, 22, 8)
    gemm1_kernel<<<grid1, 256, G_SMEM>>>();

    dim3 grid2(T_TOK / 128, HDIM / 128);        // (32, 16)
    gemm2_kernel<<<grid2, 256, G_SMEM>>>(out);
}